// round 16
// baseline (speedup 1.0000x reference)
#include <cuda_runtime.h>
#include <cuda_fp16.h>
#include <cstdint>

#define D_DIM 256
#define K_DIM 1024
#define N_ROWS 32768
#define TM 32
#define NTHR 512
#define XS_STRIDE 264
#define DS_STRIDE 1032
#define CHUNK_HALFS 32768      // 64 KB chunks
#define CHUNK_BYTES 65536
#define N_LCHUNK 8
#define N_RCHUNK 8

__device__ __align__(16) __half g_chunksL[N_LCHUNK * CHUNK_HALFS];
__device__ __align__(16) __half g_chunksR[N_RCHUNK * CHUNK_HALFS];
__device__ float g_colsum[K_DIM];
__device__ float g_lse_sum;

__device__ __forceinline__ void mma16(float* c, const uint32_t* a, uint32_t b0, uint32_t b1) {
    asm volatile(
        "mma.sync.aligned.m16n8k16.row.col.f32.f16.f16.f32 "
        "{%0,%1,%2,%3}, {%4,%5,%6,%7}, {%8,%9}, {%0,%1,%2,%3};"
        : "+f"(c[0]), "+f"(c[1]), "+f"(c[2]), "+f"(c[3])
        : "r"(a[0]), "r"(a[1]), "r"(a[2]), "r"(a[3]), "r"(b0), "r"(b1));
}
__device__ __forceinline__ void bulk_cp(uint32_t d, const void* s, uint32_t b, uint32_t m) {
    asm volatile("cp.async.bulk.shared::cta.global.mbarrier::complete_tx::bytes [%0], [%1], %2, [%3];"
                 :: "r"(d), "l"(s), "r"(b), "r"(m) : "memory");
}
__device__ __forceinline__ void mbar_init(uint32_t m, uint32_t c) {
    asm volatile("mbarrier.init.shared.b64 [%0], %1;" :: "r"(m), "r"(c) : "memory");
}
__device__ __forceinline__ void mbar_expect(uint32_t m, uint32_t b) {
    asm volatile("mbarrier.arrive.expect_tx.shared.b64 _, [%0], %1;" :: "r"(m), "r"(b) : "memory");
}
__device__ __forceinline__ void mbar_wait(uint32_t m, uint32_t p) {
    asm volatile("{\n\t.reg .pred P;\n\tW_%=: mbarrier.try_wait.parity.acquire.cta.shared::cta.b64 P, [%0], %1, 0x989680;\n\t@P bra.uni D_%=;\n\tbra.uni W_%=;\n\tD_%=:\n\t}"
                 :: "r"(m), "r"(p) : "memory");
}

__global__ void k_prep(const float* __restrict__ cb) {
    int lane = threadIdx.x & 31;
    int gw = (blockIdx.x * blockDim.x + threadIdx.x) >> 5;
    if (blockIdx.x == 0) {
        for (int k = threadIdx.x; k < K_DIM; k += blockDim.x) g_colsum[k] = 0.0f;
        if (threadIdx.x == 0) g_lse_sum = 0.0f;
    }
    if (gw >= K_DIM) return;
    const int k = gw;
    const float* row = cb + (size_t)k * D_DIM;
    float v[8]; float ss = 0.0f;
#pragma unroll
    for (int j = 0; j < 8; j++) { v[j] = row[lane + 32 * j]; ss += v[j] * v[j]; }
#pragma unroll
    for (int o = 16; o > 0; o >>= 1) ss += __shfl_xor_sync(0xffffffffu, ss, o);
    float rinv = rsqrtf(ss);
#pragma unroll
    for (int j = 0; j < 8; j++) {
        int d = lane + 32 * j;
        __half h = __float2half_rn(v[j] * rinv);
        int cl = d >> 5;
        int wl = (((d & 31) >> 1) + ((k & 6) << 1)) & 15;
        g_chunksL[(size_t)cl * CHUNK_HALFS + k * 32 + wl * 2 + (d & 1)] = h;
        int cr = k >> 7;
        int wr = (((k & 127) >> 1) + ((d & 7) << 2)) & 63;
        g_chunksR[(size_t)cr * CHUNK_HALFS + d * 128 + wr * 2 + (k & 1)] = h;
    }
}

extern __shared__ __half s_hbuf[];

__global__ __launch_bounds__(NTHR, 1) void k_main(const float* __restrict__ in,
                                                  float* __restrict__ out) {
    __half* xs  = s_hbuf;
    __half* ds  = xs + TM * XS_STRIDE;
    __half* stg = ds + TM * DS_STRIDE;
    __shared__ __align__(8) unsigned long long s_mbar[2];
    __shared__ float s_rowsum[TM], s_inv[TM], s_t2[TM], s_t3[TM];

    const int tid = threadIdx.x;
    const int warp = tid >> 5, lane = tid & 31;
    const int qr = lane >> 2, qc = lane & 3;
    const size_t base = (size_t)blockIdx.x * TM * D_DIM;

    const uint32_t stg_a = (uint32_t)__cvta_generic_to_shared(stg);
    const uint32_t mb0 = (uint32_t)__cvta_generic_to_shared(&s_mbar[0]);
    const uint32_t mb1 = (uint32_t)__cvta_generic_to_shared(&s_mbar[1]);

    if (tid < TM) { s_rowsum[tid] = 0.0f; s_t2[tid] = 0.0f; s_t3[tid] = 0.0f; }
    if (tid == 0) {
        mbar_init(mb0, 1); mbar_init(mb1, 1);
        asm volatile("fence.proxy.async.shared::cta;" ::: "memory");
    }
    __syncthreads();
    if (tid == 0) { mbar_expect(mb0, CHUNK_BYTES); bulk_cp(stg_a, g_chunksL, CHUNK_BYTES, mb0); }

    // load + normalize input rows -> fp16 (16 warps -> 2 rows each)
#pragma unroll
    for (int rr = 0; rr < 2; rr++) {
        int r = warp * 2 + rr;
        const float* rp = in + base + (size_t)r * D_DIM;
        float v[8]; float ss = 0.0f;
#pragma unroll
        for (int j = 0; j < 8; j++) { v[j] = rp[lane + 32 * j]; ss += v[j] * v[j]; }
#pragma unroll
        for (int o = 16; o > 0; o >>= 1) ss += __shfl_xor_sync(0xffffffffu, ss, o);
        float rinv = rsqrtf(ss);
#pragma unroll
        for (int j = 0; j < 8; j++)
            xs[r * XS_STRIDE + lane + 32 * j] = __float2half_rn(v[j] * rinv);
    }
    __syncthreads();

    // ---- logits: 8 chunks of 32 d.  warp w owns n in [64w, 64w+64)
    float acc[2][8][4];
#pragma unroll
    for (int mt = 0; mt < 2; mt++)
#pragma unroll
        for (int nt = 0; nt < 8; nt++)
#pragma unroll
            for (int j = 0; j < 4; j++) acc[mt][nt][j] = 0.0f;

    const int rotL = (qr & 6) << 1;
    for (int c = 0; c < N_LCHUNK; c++) {
        __half* buf = stg + (c & 1) * CHUNK_HALFS;
        if (tid == 0 && c + 1 < N_LCHUNK) {
            uint32_t b = (c + 1) & 1, mb = b ? mb1 : mb0;
            mbar_expect(mb, CHUNK_BYTES);
            bulk_cp(stg_a + b * CHUNK_BYTES, g_chunksL + (size_t)(c + 1) * CHUNK_HALFS, CHUNK_BYTES, mb);
        }
        mbar_wait((c & 1) ? mb1 : mb0, (c >> 1) & 1);

#pragma unroll
        for (int s = 0; s < 2; s++) {
            uint32_t a[2][4];
#pragma unroll
            for (int mt = 0; mt < 2; mt++) {
                const __half* xr = xs + (mt * 16 + qr) * XS_STRIDE + c * 32 + s * 16 + 2 * qc;
                a[mt][0] = *(const uint32_t*)(xr);
                a[mt][1] = *(const uint32_t*)(xr + 8 * XS_STRIDE);
                a[mt][2] = *(const uint32_t*)(xr + 8);
                a[mt][3] = *(const uint32_t*)(xr + 8 * XS_STRIDE + 8);
            }
            const int i0 = ((8 * s + qc + rotL) & 15) << 1;
            const int i1 = ((8 * s + qc + 4 + rotL) & 15) << 1;
#pragma unroll
            for (int nt = 0; nt < 8; nt++) {
                const __half* bp = buf + (warp * 64 + nt * 8 + qr) * 32;
                uint32_t b0 = *(const uint32_t*)(bp + i0);
                uint32_t b1 = *(const uint32_t*)(bp + i1);
                mma16(acc[0][nt], a[0], b0, b1);
                mma16(acc[1][nt], a[1], b0, b1);
            }
        }
        __syncthreads();
    }

    if (tid == 0) { mbar_expect(mb0, CHUNK_BYTES); bulk_cp(stg_a, g_chunksR, CHUNK_BYTES, mb0); }

    // ---- exp + row sums
    float pr[4] = {0.0f, 0.0f, 0.0f, 0.0f};
#pragma unroll
    for (int mt = 0; mt < 2; mt++)
#pragma unroll
        for (int nt = 0; nt < 8; nt++) {
            float e0 = __expf(acc[mt][nt][0]);
            float e1 = __expf(acc[mt][nt][1]);
            float e2 = __expf(acc[mt][nt][2]);
            float e3 = __expf(acc[mt][nt][3]);
            acc[mt][nt][0] = e0; acc[mt][nt][1] = e1;
            acc[mt][nt][2] = e2; acc[mt][nt][3] = e3;
            pr[2 * mt] += e0 + e1; pr[2 * mt + 1] += e2 + e3;
        }
#pragma unroll
    for (int o = 1; o <= 2; o <<= 1)
#pragma unroll
        for (int p = 0; p < 4; p++) pr[p] += __shfl_xor_sync(0xffffffffu, pr[p], o);
    if (qc == 0) {
        atomicAdd(&s_rowsum[qr],      pr[0]);
        atomicAdd(&s_rowsum[qr + 8],  pr[1]);
        atomicAdd(&s_rowsum[qr + 16], pr[2]);
        atomicAdd(&s_rowsum[qr + 24], pr[3]);
    }
    __syncthreads();
    if (tid < TM) s_inv[tid] = 1.0f / s_rowsum[tid];
    __syncthreads();

    // ---- rescale -> ds (single fp16 round); colsum; t2/t3
    {
        float iv0 = s_inv[qr], iv1 = s_inv[qr + 8], iv2 = s_inv[qr + 16], iv3 = s_inv[qr + 24];
        float t2[4] = {0, 0, 0, 0}, t3[4] = {0, 0, 0, 0};
#pragma unroll
        for (int nt = 0; nt < 8; nt++) {
            int col = warp * 64 + nt * 8 + 2 * qc;
            float cp0 = 0.0f, cp1 = 0.0f;
#pragma unroll
            for (int mt = 0; mt < 2; mt++) {
                float ivA = (mt == 0) ? iv0 : iv2;
                float ivB = (mt == 0) ? iv1 : iv3;
                float d0 = acc[mt][nt][0] * ivA;
                float d1 = acc[mt][nt][1] * ivA;
                float d2 = acc[mt][nt][2] * ivB;
                float d3 = acc[mt][nt][3] * ivB;
                int r0 = mt * 16 + qr;
                *(__half2*)(ds + r0 * DS_STRIDE + col)       = __floats2half2_rn(d0, d1);
                *(__half2*)(ds + (r0 + 8) * DS_STRIDE + col) = __floats2half2_rn(d2, d3);
                t2[2 * mt]     += d0 * d0 + d1 * d1;
                t3[2 * mt]     += d0 * d0 * d0 + d1 * d1 * d1;
                t2[2 * mt + 1] += d2 * d2 + d3 * d3;
                t3[2 * mt + 1] += d2 * d2 * d2 + d3 * d3 * d3;
                cp0 += d0 + d2; cp1 += d1 + d3;
            }
#pragma unroll
            for (int o = 4; o <= 16; o <<= 1) {
                cp0 += __shfl_xor_sync(0xffffffffu, cp0, o);
                cp1 += __shfl_xor_sync(0xffffffffu, cp1, o);
            }
            if (qr == 0) {
                atomicAdd(&g_colsum[col], cp0);
                atomicAdd(&g_colsum[col + 1], cp1);
            }
        }
#pragma unroll
        for (int o = 1; o <= 2; o <<= 1)
#pragma unroll
            for (int p = 0; p < 4; p++) {
                t2[p] += __shfl_xor_sync(0xffffffffu, t2[p], o);
                t3[p] += __shfl_xor_sync(0xffffffffu, t3[p], o);
            }
        if (qc == 0) {
#pragma unroll
            for (int p = 0; p < 4; p++) {
                atomicAdd(&s_t2[qr + 8 * p], t2[p]);
                atomicAdd(&s_t3[qr + 8 * p], t3[p]);
            }
        }
    }
    __syncthreads();
    if (tid < TM) {
        float l = __logf(1025.0f + 0.5f * s_t2[tid] + 0.16666667f * s_t3[tid]);
#pragma unroll
        for (int o = 16; o > 0; o >>= 1) l += __shfl_xor_sync(0xffffffffu, l, o);
        if (tid == 0) atomicAdd(&g_lse_sum, l);
    }

    // ---- recon: 8 chunks of 128 k.  warp w owns n in [16w, 16w+16)
    float acc2[2][2][4];
#pragma unroll
    for (int mt = 0; mt < 2; mt++)
#pragma unroll
        for (int nt = 0; nt < 2; nt++)
#pragma unroll
            for (int j = 0; j < 4; j++) acc2[mt][nt][j] = 0.0f;

    const int rotR = qr << 2;
    for (int c = 0; c < N_RCHUNK; c++) {
        __half* buf = stg + (c & 1) * CHUNK_HALFS;
        if (tid == 0 && c + 1 < N_RCHUNK) {
            uint32_t b = (c + 1) & 1, mb = b ? mb1 : mb0;
            mbar_expect(mb, CHUNK_BYTES);
            bulk_cp(stg_a + b * CHUNK_BYTES, g_chunksR + (size_t)(c + 1) * CHUNK_HALFS, CHUNK_BYTES, mb);
        }
        mbar_wait((c & 1) ? mb1 : mb0, (c >> 1) & 1);

#pragma unroll
        for (int ks = 0; ks < 8; ks++) {
            uint32_t a[2][4];
#pragma unroll
            for (int mt = 0; mt < 2; mt++) {
                const __half* dr = ds + (mt * 16 + qr) * DS_STRIDE + c * 128 + ks * 16 + 2 * qc;
                a[mt][0] = *(const uint32_t*)(dr);
                a[mt][1] = *(const uint32_t*)(dr + 8 * DS_STRIDE);
                a[mt][2] = *(const uint32_t*)(dr + 8);
                a[mt][3] = *(const uint32_t*)(dr + 8 * DS_STRIDE + 8);
            }
            const int i0 = ((ks * 8 + qc + rotR) & 63) << 1;
            const int i1 = ((ks * 8 + qc + 4 + rotR) & 63) << 1;
#pragma unroll
            for (int nt = 0; nt < 2; nt++) {
                const __half* bp = buf + (warp * 16 + nt * 8 + qr) * 128;
                uint32_t b0 = *(const uint32_t*)(bp + i0);
                uint32_t b1 = *(const uint32_t*)(bp + i1);
                mma16(acc2[0][nt], a[0], b0, b1);
                mma16(acc2[1][nt], a[1], b0, b1);
            }
        }
        __syncthreads();
    }

#pragma unroll
    for (int mt = 0; mt < 2; mt++)
#pragma unroll
        for (int nt = 0; nt < 2; nt++) {
            int r0 = mt * 16 + qr;
            int col = warp * 16 + nt * 8 + 2 * qc;
            *reinterpret_cast<float2*>(out + base + (size_t)r0 * D_DIM + col) =
                make_float2(acc2[mt][nt][0], acc2[mt][nt][1]);
            *reinterpret_cast<float2*>(out + base + (size_t)(r0 + 8) * D_DIM + col) =
                make_float2(acc2[mt][nt][2], acc2[mt][nt][3]);
        }
}

__global__ void k_loss(float* __restrict__ out, int out_size) {
    __shared__ float red[8];
    int tid = threadIdx.x;
    float s = 0.0f;
    for (int k = tid; k < K_DIM; k += 256) { float c = g_colsum[k]; s += c * c; }
#pragma unroll
    for (int o = 16; o > 0; o >>= 1) s += __shfl_xor_sync(0xffffffffu, s, o);
    if ((tid & 31) == 0) red[tid >> 5] = s;
    __syncthreads();
    if (tid == 0) {
        float t = 0.0f;
#pragma unroll
        for (int w = 0; w < 8; w++) t += red[w];
        float entropy = g_lse_sum - t / (float)N_ROWS;
        out[out_size - 1] = 1000.0f * (1.0f / (float)K_DIM) + 5e-5f * entropy;
    }
}

extern "C" void kernel_launch(void* const* d_in, const int* in_sizes, int n_in,
                              void* d_out, int out_size) {
    const float* in = (const float*)d_in[0];
    const float* cb = (const float*)d_in[1];
    float* out = (float*)d_out;
    (void)in_sizes; (void)n_in;
    const size_t smem = (size_t)(TM * XS_STRIDE + TM * DS_STRIDE + 2 * CHUNK_HALFS) * sizeof(__half);
    cudaFuncSetAttribute(k_main, cudaFuncAttributeMaxDynamicSharedMemorySize, (int)smem);
    k_prep<<<K_DIM / 8, 256>>>(cb);
    k_main<<<N_ROWS / TM, NTHR, smem>>>(in, out);
    k_loss<<<1, 256>>>(out, out_size);
}

// round 17
// speedup vs baseline: 1.1793x; 1.1793x over previous
#include <cuda_runtime.h>
#include <cuda_fp16.h>
#include <cstdint>

#define D_DIM 256
#define K_DIM 1024
#define N_ROWS 32768
#define TM 32
#define NTHR 256
#define XS_STRIDE 264
#define DS_STRIDE 1032
#define CHUNK_HALFS 32768
#define CHUNK_BYTES 65536
#define N_LCHUNK 8
#define N_RCHUNK 8

__device__ __align__(16) __half g_chunksL[N_LCHUNK * CHUNK_HALFS];
__device__ __align__(16) __half g_chunksR[N_RCHUNK * CHUNK_HALFS];
__device__ float g_colsum[K_DIM];
__device__ float g_lse_sum;
__device__ int   g_done;

__device__ __forceinline__ void mma16(float* c, const uint32_t* a, uint32_t b0, uint32_t b1) {
    asm volatile(
        "mma.sync.aligned.m16n8k16.row.col.f32.f16.f16.f32 "
        "{%0,%1,%2,%3}, {%4,%5,%6,%7}, {%8,%9}, {%0,%1,%2,%3};"
        : "+f"(c[0]), "+f"(c[1]), "+f"(c[2]), "+f"(c[3])
        : "r"(a[0]), "r"(a[1]), "r"(a[2]), "r"(a[3]), "r"(b0), "r"(b1));
}
__device__ __forceinline__ void bulk_cp(uint32_t d, const void* s, uint32_t b, uint32_t m) {
    asm volatile("cp.async.bulk.shared::cta.global.mbarrier::complete_tx::bytes [%0], [%1], %2, [%3];"
                 :: "r"(d), "l"(s), "r"(b), "r"(m) : "memory");
}
__device__ __forceinline__ void mbar_init(uint32_t m, uint32_t c) {
    asm volatile("mbarrier.init.shared.b64 [%0], %1;" :: "r"(m), "r"(c) : "memory");
}
__device__ __forceinline__ void mbar_expect(uint32_t m, uint32_t b) {
    asm volatile("mbarrier.arrive.expect_tx.shared.b64 _, [%0], %1;" :: "r"(m), "r"(b) : "memory");
}
__device__ __forceinline__ void mbar_wait(uint32_t m, uint32_t p) {
    asm volatile("{\n\t.reg .pred P;\n\tW_%=: mbarrier.try_wait.parity.acquire.cta.shared::cta.b64 P, [%0], %1, 0x989680;\n\t@P bra.uni D_%=;\n\tbra.uni W_%=;\n\tD_%=:\n\t}"
                 :: "r"(m), "r"(p) : "memory");
}

__global__ void k_prep(const float* __restrict__ cb) {
    int lane = threadIdx.x & 31;
    int gw = (blockIdx.x * blockDim.x + threadIdx.x) >> 5;
    if (blockIdx.x == 0) {
        for (int k = threadIdx.x; k < K_DIM; k += blockDim.x) g_colsum[k] = 0.0f;
        if (threadIdx.x == 0) { g_lse_sum = 0.0f; g_done = 0; }
    }
    if (gw >= K_DIM) return;
    const int k = gw;
    const float* row = cb + (size_t)k * D_DIM;
    float v[8]; float ss = 0.0f;
#pragma unroll
    for (int j = 0; j < 8; j++) { v[j] = row[lane + 32 * j]; ss += v[j] * v[j]; }
#pragma unroll
    for (int o = 16; o > 0; o >>= 1) ss += __shfl_xor_sync(0xffffffffu, ss, o);
    float rinv = rsqrtf(ss);
#pragma unroll
    for (int j = 0; j < 8; j++) {
        int d = lane + 32 * j;
        __half h = __float2half_rn(v[j] * rinv);
        int cl = d >> 5;
        int wl = (((d & 31) >> 1) + ((k & 6) << 1)) & 15;
        g_chunksL[(size_t)cl * CHUNK_HALFS + k * 32 + wl * 2 + (d & 1)] = h;
        int cr = k >> 7;
        int wr = (((k & 127) >> 1) + ((d & 7) << 2)) & 63;
        g_chunksR[(size_t)cr * CHUNK_HALFS + d * 128 + wr * 2 + (k & 1)] = h;
    }
}

extern __shared__ __half s_hbuf[];

__global__ __launch_bounds__(NTHR, 1) void k_main(const float* __restrict__ in,
                                                  float* __restrict__ out, int out_size,
                                                  int nblocks) {
    __half* xs  = s_hbuf;
    __half* ds  = xs + TM * XS_STRIDE;
    __half* stg = ds + TM * DS_STRIDE;
    __shared__ __align__(8) unsigned long long s_mbar[3];
    __shared__ float s_rowsum[TM], s_inv[TM], s_t2[TM], s_t3[TM];
    __shared__ int s_last;

    const int tid = threadIdx.x;
    const int warp = tid >> 5, lane = tid & 31;
    const int qr = lane >> 2, qc = lane & 3;
    const size_t base = (size_t)blockIdx.x * TM * D_DIM;

    const uint32_t stg_a = (uint32_t)__cvta_generic_to_shared(stg);
    const uint32_t ds_a  = (uint32_t)__cvta_generic_to_shared(ds);
    const uint32_t mb0 = (uint32_t)__cvta_generic_to_shared(&s_mbar[0]);
    const uint32_t mb1 = (uint32_t)__cvta_generic_to_shared(&s_mbar[1]);
    const uint32_t mb2 = (uint32_t)__cvta_generic_to_shared(&s_mbar[2]);

    if (tid < TM) { s_rowsum[tid] = 0.0f; s_t2[tid] = 0.0f; s_t3[tid] = 0.0f; }
    if (tid == 0) {
        mbar_init(mb0, 1); mbar_init(mb1, 1); mbar_init(mb2, 1);
        asm volatile("fence.proxy.async.shared::cta;" ::: "memory");
    }
    __syncthreads();
    if (tid == 0) {
        mbar_expect(mb2, TM * D_DIM * 4);
        bulk_cp(ds_a, in + base, TM * D_DIM * 4, mb2);      // input tile -> ds region (fp32)
        mbar_expect(mb0, CHUNK_BYTES);
        bulk_cp(stg_a, g_chunksL, CHUNK_BYTES, mb0);
    }
    mbar_wait(mb2, 0);

    // normalize input rows from SMEM -> fp16 in xs
    const float* dsf = (const float*)ds;
#pragma unroll
    for (int rr = 0; rr < 4; rr++) {
        int r = warp * 4 + rr;
        float v[8]; float ss = 0.0f;
#pragma unroll
        for (int j = 0; j < 8; j++) { v[j] = dsf[r * D_DIM + lane + 32 * j]; ss += v[j] * v[j]; }
#pragma unroll
        for (int o = 16; o > 0; o >>= 1) ss += __shfl_xor_sync(0xffffffffu, ss, o);
        float rinv = rsqrtf(ss);
#pragma unroll
        for (int j = 0; j < 8; j++)
            xs[r * XS_STRIDE + lane + 32 * j] = __float2half_rn(v[j] * rinv);
    }
    __syncthreads();

    // ---- logits: 8 chunks of 32 d
    float acc[2][16][4];
#pragma unroll
    for (int mt = 0; mt < 2; mt++)
#pragma unroll
        for (int nt = 0; nt < 16; nt++)
#pragma unroll
            for (int j = 0; j < 4; j++) acc[mt][nt][j] = 0.0f;

    const int rotL = (qr & 6) << 1;
#pragma unroll
    for (int c = 0; c < N_LCHUNK; c++) {
        __half* buf = stg + (c & 1) * CHUNK_HALFS;
        if (tid == 0 && c + 1 < N_LCHUNK) {
            uint32_t b = (c + 1) & 1, mb = b ? mb1 : mb0;
            mbar_expect(mb, CHUNK_BYTES);
            bulk_cp(stg_a + b * CHUNK_BYTES, g_chunksL + (size_t)(c + 1) * CHUNK_HALFS, CHUNK_BYTES, mb);
        }
        mbar_wait((c & 1) ? mb1 : mb0, (c >> 1) & 1);

#pragma unroll
        for (int s = 0; s < 2; s++) {
            uint32_t a[2][4];
#pragma unroll
            for (int mt = 0; mt < 2; mt++) {
                const __half* xr = xs + (mt * 16 + qr) * XS_STRIDE + c * 32 + s * 16 + 2 * qc;
                a[mt][0] = *(const uint32_t*)(xr);
                a[mt][1] = *(const uint32_t*)(xr + 8 * XS_STRIDE);
                a[mt][2] = *(const uint32_t*)(xr + 8);
                a[mt][3] = *(const uint32_t*)(xr + 8 * XS_STRIDE + 8);
            }
            const int i0 = ((8 * s + qc + rotL) & 15) << 1;
            const int i1 = ((8 * s + qc + 4 + rotL) & 15) << 1;
#pragma unroll
            for (int nt = 0; nt < 16; nt++) {
                const __half* bp = buf + (warp * 128 + nt * 8 + qr) * 32;
                uint32_t b0 = *(const uint32_t*)(bp + i0);
                uint32_t b1 = *(const uint32_t*)(bp + i1);
                mma16(acc[0][nt], a[0], b0, b1);
                mma16(acc[1][nt], a[1], b0, b1);
            }
        }
        __syncthreads();
    }

    if (tid == 0) { mbar_expect(mb0, CHUNK_BYTES); bulk_cp(stg_a, g_chunksR, CHUNK_BYTES, mb0); }

    // ---- exp + row sums
    float pr[4] = {0.0f, 0.0f, 0.0f, 0.0f};
#pragma unroll
    for (int mt = 0; mt < 2; mt++)
#pragma unroll
        for (int nt = 0; nt < 16; nt++) {
            float e0 = __expf(acc[mt][nt][0]);
            float e1 = __expf(acc[mt][nt][1]);
            float e2 = __expf(acc[mt][nt][2]);
            float e3 = __expf(acc[mt][nt][3]);
            acc[mt][nt][0] = e0; acc[mt][nt][1] = e1;
            acc[mt][nt][2] = e2; acc[mt][nt][3] = e3;
            pr[2 * mt] += e0 + e1; pr[2 * mt + 1] += e2 + e3;
        }
#pragma unroll
    for (int o = 1; o <= 2; o <<= 1)
#pragma unroll
        for (int p = 0; p < 4; p++) pr[p] += __shfl_xor_sync(0xffffffffu, pr[p], o);
    if (qc == 0) {
        atomicAdd(&s_rowsum[qr],      pr[0]);
        atomicAdd(&s_rowsum[qr + 8],  pr[1]);
        atomicAdd(&s_rowsum[qr + 16], pr[2]);
        atomicAdd(&s_rowsum[qr + 24], pr[3]);
    }
    __syncthreads();
    if (tid < TM) s_inv[tid] = 1.0f / s_rowsum[tid];
    __syncthreads();

    // ---- rescale -> ds (single fp16 round); colsum; t2/t3
    {
        float iv0 = s_inv[qr], iv1 = s_inv[qr + 8], iv2 = s_inv[qr + 16], iv3 = s_inv[qr + 24];
        float t2[4] = {0, 0, 0, 0}, t3[4] = {0, 0, 0, 0};
#pragma unroll
        for (int nt = 0; nt < 16; nt++) {
            int col = warp * 128 + nt * 8 + 2 * qc;
            float cp0 = 0.0f, cp1 = 0.0f;
#pragma unroll
            for (int mt = 0; mt < 2; mt++) {
                float ivA = (mt == 0) ? iv0 : iv2;
                float ivB = (mt == 0) ? iv1 : iv3;
                float d0 = acc[mt][nt][0] * ivA;
                float d1 = acc[mt][nt][1] * ivA;
                float d2 = acc[mt][nt][2] * ivB;
                float d3 = acc[mt][nt][3] * ivB;
                int r0 = mt * 16 + qr;
                *(__half2*)(ds + r0 * DS_STRIDE + col)       = __floats2half2_rn(d0, d1);
                *(__half2*)(ds + (r0 + 8) * DS_STRIDE + col) = __floats2half2_rn(d2, d3);
                t2[2 * mt]     += d0 * d0 + d1 * d1;
                t3[2 * mt]     += d0 * d0 * d0 + d1 * d1 * d1;
                t2[2 * mt + 1] += d2 * d2 + d3 * d3;
                t3[2 * mt + 1] += d2 * d2 * d2 + d3 * d3 * d3;
                cp0 += d0 + d2; cp1 += d1 + d3;
            }
#pragma unroll
            for (int o = 4; o <= 16; o <<= 1) {
                cp0 += __shfl_xor_sync(0xffffffffu, cp0, o);
                cp1 += __shfl_xor_sync(0xffffffffu, cp1, o);
            }
            if (qr == 0) {
                atomicAdd(&g_colsum[col], cp0);
                atomicAdd(&g_colsum[col + 1], cp1);
            }
        }
#pragma unroll
        for (int o = 1; o <= 2; o <<= 1)
#pragma unroll
            for (int p = 0; p < 4; p++) {
                t2[p] += __shfl_xor_sync(0xffffffffu, t2[p], o);
                t3[p] += __shfl_xor_sync(0xffffffffu, t3[p], o);
            }
        if (qc == 0) {
#pragma unroll
            for (int p = 0; p < 4; p++) {
                atomicAdd(&s_t2[qr + 8 * p], t2[p]);
                atomicAdd(&s_t3[qr + 8 * p], t3[p]);
            }
        }
    }
    __syncthreads();
    if (tid < TM) {
        float l = __logf(1025.0f + 0.5f * s_t2[tid] + 0.16666667f * s_t3[tid]);
#pragma unroll
        for (int o = 16; o > 0; o >>= 1) l += __shfl_xor_sync(0xffffffffu, l, o);
        if (tid == 0) atomicAdd(&g_lse_sum, l);
    }

    // ---- recon: 8 chunks of 128 k
    float acc2[2][4][4];
#pragma unroll
    for (int mt = 0; mt < 2; mt++)
#pragma unroll
        for (int nt = 0; nt < 4; nt++)
#pragma unroll
            for (int j = 0; j < 4; j++) acc2[mt][nt][j] = 0.0f;

    const int rotR = qr << 2;
#pragma unroll
    for (int c = 0; c < N_RCHUNK; c++) {
        __half* buf = stg + (c & 1) * CHUNK_HALFS;
        if (tid == 0 && c + 1 < N_RCHUNK) {
            uint32_t b = (c + 1) & 1, mb = b ? mb1 : mb0;
            mbar_expect(mb, CHUNK_BYTES);
            bulk_cp(stg_a + b * CHUNK_BYTES, g_chunksR + (size_t)(c + 1) * CHUNK_HALFS, CHUNK_BYTES, mb);
        }
        mbar_wait((c & 1) ? mb1 : mb0, (c >> 1) & 1);

#pragma unroll
        for (int ks = 0; ks < 8; ks++) {
            uint32_t a[2][4];
#pragma unroll
            for (int mt = 0; mt < 2; mt++) {
                const __half* dr = ds + (mt * 16 + qr) * DS_STRIDE + c * 128 + ks * 16 + 2 * qc;
                a[mt][0] = *(const uint32_t*)(dr);
                a[mt][1] = *(const uint32_t*)(dr + 8 * DS_STRIDE);
                a[mt][2] = *(const uint32_t*)(dr + 8);
                a[mt][3] = *(const uint32_t*)(dr + 8 * DS_STRIDE + 8);
            }
            const int i0 = ((ks * 8 + qc + rotR) & 63) << 1;
            const int i1 = ((ks * 8 + qc + 4 + rotR) & 63) << 1;
#pragma unroll
            for (int nt = 0; nt < 4; nt++) {
                const __half* bp = buf + (warp * 32 + nt * 8 + qr) * 128;
                uint32_t b0 = *(const uint32_t*)(bp + i0);
                uint32_t b1 = *(const uint32_t*)(bp + i1);
                mma16(acc2[0][nt], a[0], b0, b1);
                mma16(acc2[1][nt], a[1], b0, b1);
            }
        }
        __syncthreads();
    }

#pragma unroll
    for (int mt = 0; mt < 2; mt++)
#pragma unroll
        for (int nt = 0; nt < 4; nt++) {
            int r0 = mt * 16 + qr;
            int col = warp * 32 + nt * 8 + 2 * qc;
            *reinterpret_cast<float2*>(out + base + (size_t)r0 * D_DIM + col) =
                make_float2(acc2[mt][nt][0], acc2[mt][nt][1]);
            *reinterpret_cast<float2*>(out + base + (size_t)(r0 + 8) * D_DIM + col) =
                make_float2(acc2[mt][nt][2], acc2[mt][nt][3]);
        }

    // ---- last CTA computes the loss (replaces k_loss launch)
    __threadfence();
    __syncthreads();
    if (tid == 0) s_last = (atomicAdd(&g_done, 1) == nblocks - 1);
    __syncthreads();
    if (s_last) {
        __shared__ float red[8];
        float s = 0.0f;
        for (int k = tid; k < K_DIM; k += NTHR) { float c = g_colsum[k]; s += c * c; }
#pragma unroll
        for (int o = 16; o > 0; o >>= 1) s += __shfl_xor_sync(0xffffffffu, s, o);
        if ((tid & 31) == 0) red[tid >> 5] = s;
        __syncthreads();
        if (tid == 0) {
            float t = 0.0f;
#pragma unroll
            for (int w = 0; w < 8; w++) t += red[w];
            float entropy = g_lse_sum - t / (float)N_ROWS;
            out[out_size - 1] = 1000.0f * (1.0f / (float)K_DIM) + 5e-5f * entropy;
        }
    }
}

extern "C" void kernel_launch(void* const* d_in, const int* in_sizes, int n_in,
                              void* d_out, int out_size) {
    const float* in = (const float*)d_in[0];
    const float* cb = (const float*)d_in[1];
    float* out = (float*)d_out;
    (void)in_sizes; (void)n_in;
    const size_t smem = (size_t)(TM * XS_STRIDE + TM * DS_STRIDE + 2 * CHUNK_HALFS) * sizeof(__half);
    cudaFuncSetAttribute(k_main, cudaFuncAttributeMaxDynamicSharedMemorySize, (int)smem);
    k_prep<<<K_DIM / 8, 256>>>(cb);
    k_main<<<N_ROWS / TM, NTHR, smem>>>(in, out, out_size, N_ROWS / TM);
}